// round 12
// baseline (speedup 1.0000x reference)
#include <cuda_runtime.h>
#include <math.h>
#include <cstdint>

#define BATCH 256
#define NBOX 98
#define KTOP 10

// ---------------- scratch (static device globals; no allocation) ----------------
__device__ float g_A0[12544 * 1280];       // gathered subsampled input, M x K
__device__ float g_part[3 * 12544 * 128];  // split-K partials (max consumer: conv)
__device__ float g_act1[BATCH * 6272];     // conv output in fc1-input layout
__device__ float g_h1[BATCH * 4096];       // fc1 output (post leaky relu)
__device__ float g_h2[BATCH * 1470];       // fc2 output (post sigmoid)
__device__ float g_boxes[BATCH * NBOX * 4];
__device__ float g_conf[BATCH * NBOX];
__device__ int   g_labels[BATCH * NBOX];

// ---------------- helpers -------------------------------------------------------
__device__ __forceinline__ uint32_t smem_u32(const void* p) {
    uint32_t a;
    asm("{ .reg .u64 t; cvta.to.shared.u64 t, %1; cvt.u32.u64 %0, t; }"
        : "=r"(a) : "l"(p));
    return a;
}
__device__ __forceinline__ void cp4(uint32_t dst, const void* src) {
    asm volatile("cp.async.ca.shared.global [%0], [%1], 4;" :: "r"(dst), "l"(src));
}
#define CP_COMMIT() asm volatile("cp.async.commit_group;" ::: "memory")
#define CP_WAIT1()  asm volatile("cp.async.wait_group 1;" ::: "memory")

// Fast 3xTF32 split: the tensor core reads only the 19 tf32 bits of a .b32
// operand (low 13 mantissa bits ignored). hi = a masked to tf32 bits;
// r = a - hi is exact (Sterbenz); r is fed raw as lo (MMA truncates it).
__device__ __forceinline__ void tf32_split(float a, uint32_t& hi, uint32_t& lo) {
    uint32_t ab = __float_as_uint(a) & 0xFFFFE000u;
    hi = ab;
    lo = __float_as_uint(a - __uint_as_float(ab));
}

__device__ __forceinline__ void mma_tf32(float* c, uint32_t a0, uint32_t a1,
                                         uint32_t a2, uint32_t a3,
                                         uint32_t b0, uint32_t b1) {
    asm volatile(
        "mma.sync.aligned.m16n8k8.row.col.f32.tf32.tf32.f32 "
        "{%0,%1,%2,%3}, {%4,%5,%6,%7}, {%8,%9}, {%0,%1,%2,%3};"
        : "+f"(c[0]), "+f"(c[1]), "+f"(c[2]), "+f"(c[3])
        : "r"(a0), "r"(a1), "r"(a2), "r"(a3), "r"(b0), "r"(b1));
}

// ---------------- gather: x[:, :, ::2, ::2] -> A0[m=b*49+hw][c] ------------------
__global__ void gather_kernel(const float* __restrict__ x) {
    __shared__ float tile[64][50];
    const int b  = blockIdx.y;
    const int c0 = blockIdx.x * 64;
    const int t  = threadIdx.x;
    for (int lin = t; lin < 64 * 49; lin += 256) {
        int c = lin / 49, hw = lin % 49;
        tile[c][hw] =
            x[((size_t)(b * 1280 + c0 + c) * 14 + (hw / 7) * 2) * 14 + (hw % 7) * 2];
    }
    __syncthreads();
    for (int lin = t; lin < 64 * 49; lin += 256) {
        int hw = lin >> 6, c = lin & 63;
        g_A0[((size_t)b * 49 + hw) * 1280 + c0 + c] = tile[c][hw];
    }
}

// ---------------- 3xTF32 mma.sync GEMM, BK=32 stages, 3-stage pipeline -----------
// CTA tile 128x128, K staged in chunks of 32 (2 x 16-k sub-chunks per stage).
// 8 warps: 2(m) x 4(n); warp tile 64x32.
// Stage layout (8192 words): A k-sub0 @0, A k-sub1 @2048, B k-sub0 @4096,
// B k-sub1 @6144. Each seg = 128 words = 32 lanes x 16B (fragment-major).
// __launch_bounds__(256, 2): 128 regs + 96KB smem -> 2 CTAs/SM; grids > 148.
#define STAGE_WORDS 8192
#define DSMEM_BYTES (3 * STAGE_WORDS * 4)

__device__ __forceinline__ void load_stage(
    uint32_t su, int buf, const float* __restrict__ A, const float* __restrict__ B,
    int K, const int* rowA, const int* rowB, int kb, int wid, int lane, int tig)
{
    uint32_t base = su + buf * (STAGE_WORDS * 4);
#pragma unroll
    for (int ch = 0; ch < 2; ch++) {
#pragma unroll
        for (int i = 0; i < 2; i++) {
            int seg = wid + i * 8;
            uint32_t da = base + (uint32_t)(ch * 2048 + seg * 128 + lane * 4) * 4;
            uint32_t db = da + 4096 * 4;
            const float* sa = A + (size_t)rowA[i] * K + kb + ch * 16 + tig;
            const float* sb = B + (size_t)rowB[i] * K + kb + ch * 16 + tig;
#pragma unroll
            for (int v = 0; v < 4; v++) {
                cp4(da + v * 4, sa + 4 * v);
                cp4(db + v * 4, sb + 4 * v);
            }
        }
    }
}

__global__ void __launch_bounds__(256, 2)
gemm_mma(const float* __restrict__ A, const float* __restrict__ B,
         float* __restrict__ P, int M, int N, int K, int kc, int Npad) {
    extern __shared__ __align__(16) uint32_t sm[];
    const uint32_t su = smem_u32(sm);

    const int tid  = threadIdx.x;
    const int wid  = tid >> 5;
    const int lane = tid & 31;
    const int g    = lane >> 2;
    const int tig  = lane & 3;
    const int wm   = wid >> 2;
    const int wn   = wid & 3;

    const int m0 = blockIdx.y * 128;
    const int n0 = blockIdx.x * 128;
    const int k0 = blockIdx.z * kc;
    const int nstages = (min(kc, K - k0)) >> 5;   // BK = 32

    int rowA[2], rowB[2];
#pragma unroll
    for (int i = 0; i < 2; i++) {
        int sA = wid + i * 8;
        rowA[i] = m0 + (sA >> 1) * 16 + (sA & 1) * 8 + g;
        int nr = n0 + (wid + i * 8) * 8 + g;
        rowB[i] = (nr < N) ? nr : (N - 1);
    }

    float acc[4][4][4];
#pragma unroll
    for (int a = 0; a < 4; a++)
#pragma unroll
        for (int b = 0; b < 4; b++)
#pragma unroll
            for (int c = 0; c < 4; c++) acc[a][b][c] = 0.f;

    // prologue: issue stages 0,1
    load_stage(su, 0, A, B, K, rowA, rowB, k0, wid, lane, tig);
    CP_COMMIT();
    if (nstages > 1)
        load_stage(su, 1, A, B, K, rowA, rowB, k0 + 32, wid, lane, tig);
    CP_COMMIT();

    for (int t = 0; t < nstages; t++) {
        CP_WAIT1();
        __syncthreads();
        if (t + 2 < nstages)
            load_stage(su, (t + 2) % 3, A, B, K, rowA, rowB, k0 + (t + 2) * 32,
                       wid, lane, tig);
        CP_COMMIT();

        const uint32_t* stg = sm + (t % 3) * STAGE_WORDS;

#pragma unroll
        for (int ch = 0; ch < 2; ch++) {
            const uint32_t* sbA = stg + ch * 2048;
            const uint32_t* sbB = stg + 4096 + ch * 2048;

            uint32_t Bh[4][4], Bl[4][4];
#pragma unroll
            for (int nt = 0; nt < 4; nt++) {
                uint4 raw = *(const uint4*)&sbB[(wn * 4 + nt) * 128 + lane * 4];
                const float* f = (const float*)&raw;
#pragma unroll
                for (int v = 0; v < 4; v++) tf32_split(f[v], Bh[nt][v], Bl[nt][v]);
            }

#pragma unroll
            for (int mt = 0; mt < 4; mt++) {
                int segLo = ((wm * 4 + mt) * 2) * 128;
                uint4 rlo = *(const uint4*)&sbA[segLo + lane * 4];
                uint4 rhi = *(const uint4*)&sbA[segLo + 128 + lane * 4];
                const float* flo = (const float*)&rlo;
                const float* fhi = (const float*)&rhi;
                uint32_t HLh[4], HLl[4], HHh[4], HHl[4];
#pragma unroll
                for (int v = 0; v < 4; v++) {
                    tf32_split(flo[v], HLh[v], HLl[v]);
                    tf32_split(fhi[v], HHh[v], HHl[v]);
                }
#pragma unroll
                for (int s2 = 0; s2 < 2; s2++) {
                    const int v0 = 2 * s2, v1 = 2 * s2 + 1;
#pragma unroll
                    for (int nt = 0; nt < 4; nt++) {
                        float* c = acc[mt][nt];
                        mma_tf32(c, HLh[v0], HHh[v0], HLh[v1], HHh[v1],
                                 Bh[nt][v0], Bh[nt][v1]);
                        mma_tf32(c, HLl[v0], HHl[v0], HLl[v1], HHl[v1],
                                 Bh[nt][v0], Bh[nt][v1]);
                        mma_tf32(c, HLh[v0], HHh[v0], HLh[v1], HHh[v1],
                                 Bl[nt][v0], Bl[nt][v1]);
                    }
                }
            }
        }
    }

    // ---- epilogue: write partials ----
    float* Pz = P + (size_t)blockIdx.z * M * Npad;
    const int mbase = m0 + wm * 64;
    const int nbase = n0 + wn * 32;
#pragma unroll
    for (int mt = 0; mt < 4; mt++) {
#pragma unroll
        for (int nt = 0; nt < 4; nt++) {
            float* c = acc[mt][nt];
            int r = mbase + mt * 16 + g;
            int cc = nbase + nt * 8 + tig * 2;
            *(float2*)&Pz[(size_t)r * Npad + cc]       = make_float2(c[0], c[1]);
            *(float2*)&Pz[(size_t)(r + 8) * Npad + cc] = make_float2(c[2], c[3]);
        }
    }
}

// ---------------- split-K reduces with fused epilogues --------------------------
__global__ void reduce_conv(const float* __restrict__ part,
                            const float* __restrict__ bias) {
    int idx = blockIdx.x * blockDim.x + threadIdx.x;
    if (idx >= 12544 * 128) return;
    const int S = 12544 * 128;
    int col = idx & 127;
    int m   = idx >> 7;
    float v = part[idx] + part[S + idx] + part[2 * S + idx] + bias[col];
    int b = m / 49, hw = m - b * 49;
    g_act1[(size_t)b * 6272 + col * 49 + hw] = v;
}

__global__ void reduce_fc1(const float* __restrict__ part,
                           const float* __restrict__ bias) {
    int idx = blockIdx.x * blockDim.x + threadIdx.x;
    if (idx >= 256 * 4096) return;
    const int S = 256 * 4096;
    int n = idx & 4095;
    float v = part[idx] + part[S + idx] + part[2 * S + idx] + part[3 * S + idx]
            + bias[n];
    g_h1[idx] = (v >= 0.f) ? v : 0.1f * v;
}

__global__ void reduce_fc2(const float* __restrict__ part,
                           const float* __restrict__ bias) {
    int idx = blockIdx.x * blockDim.x + threadIdx.x;
    if (idx >= 256 * 1470) return;
    int m = idx / 1470, n = idx - m * 1470;
    float v = 0.f;
#pragma unroll
    for (int s = 0; s < 12; s++) v += part[(size_t)s * 256 * 1536 + m * 1536 + n];
    v += bias[n];
    g_h2[idx] = 1.f / (1.f + expf(-v));
}

// ---------------- decode: h2 -> boxes / conf / labels ---------------------------
__global__ void decode_kernel() {
    int idx = blockIdx.x * blockDim.x + threadIdx.x;
    if (idx >= BATCH * NBOX) return;
    int b = idx / NBOX, n = idx % NBOX;
    int cell = n >> 1;
    int gi = cell / 7, gj = cell % 7;
    const float* h = g_h2 + (size_t)b * 1470;

    float bx = h[n * 4 + 0], by = h[n * 4 + 1];
    float bw = h[n * 4 + 2], bh = h[n * 4 + 3];
    float cx = bx * 64.f + gi * 64.f;
    float cy = by * 64.f + gj * 64.f;
    float w  = bw * 448.f;
    float hh = bh * 448.f;
    float x1 = fminf(fmaxf(cx - 0.5f * w,  0.f), 448.f);
    float y1 = fminf(fmaxf(cy - 0.5f * hh, 0.f), 448.f);
    float x2 = fminf(fmaxf(cx + 0.5f * w,  0.f), 448.f);
    float y2 = fminf(fmaxf(cy + 0.5f * hh, 0.f), 448.f);

    g_boxes[idx * 4 + 0] = x1;
    g_boxes[idx * 4 + 1] = y1;
    g_boxes[idx * 4 + 2] = x2;
    g_boxes[idx * 4 + 3] = y2;
    g_conf[idx] = h[392 + n];

    const float* cl = h + 490 + cell * 20;
    float best = cl[0];
    int lab = 0;
#pragma unroll
    for (int c = 1; c < 20; c++) {
        float v = cl[c];
        if (v > best) { best = v; lab = c; }  // first max wins (matches jnp.argmax)
    }
    g_labels[idx] = lab;
}

// ---------------- NMS: one block per image --------------------------------------
__global__ void __launch_bounds__(128)
nms_kernel(float* __restrict__ out, int out_size) {
    int b = blockIdx.x;
    int t = threadIdx.x;

    __shared__ float sc[NBOX], sx1[NBOX], sy1[NBOX], sx2[NBOX], sy2[NBOX];
    __shared__ int   sl[NBOX], order[NBOX];
    __shared__ float oc[NBOX], ox1[NBOX], oy1[NBOX], ox2[NBOX], oy2[NBOX], oarea[NBOX];
    __shared__ int   ol[NBOX];
    __shared__ unsigned char keep[NBOX];

    if (t < NBOX) {
        int g = b * NBOX + t;
        sc[t]  = g_conf[g];
        sl[t]  = g_labels[g];
        sx1[t] = g_boxes[g * 4 + 0];
        sy1[t] = g_boxes[g * 4 + 1];
        sx2[t] = g_boxes[g * 4 + 2];
        sy2[t] = g_boxes[g * 4 + 3];
    }
    __syncthreads();

    if (t < NBOX) {
        float c = sc[t];
        int r = 0;
        for (int j = 0; j < NBOX; j++) {
            float cj = sc[j];
            r += (cj > c) || (cj == c && j < t);
        }
        order[r] = t;
    }
    __syncthreads();

    if (t < NBOX) {
        int s = order[t];
        oc[t] = sc[s];  ol[t] = sl[s];
        ox1[t] = sx1[s]; oy1[t] = sy1[s];
        ox2[t] = sx2[s]; oy2[t] = sy2[s];
        oarea[t] = fmaxf(ox2[t] - ox1[t], 0.f) * fmaxf(oy2[t] - oy1[t], 0.f);
        keep[t] = (oc[t] > 0.1f) ? (unsigned char)1 : (unsigned char)0;
    }
    __syncthreads();

    for (int i = 0; i < NBOX; i++) {
        if (keep[i] && t < NBOX && t > i) {
            float ix1 = fmaxf(ox1[i], ox1[t]);
            float iy1 = fmaxf(oy1[i], oy1[t]);
            float ix2 = fminf(ox2[i], ox2[t]);
            float iy2 = fminf(oy2[i], oy2[t]);
            float inter = fmaxf(ix2 - ix1, 0.f) * fmaxf(iy2 - iy1, 0.f);
            float uni = oarea[i] + oarea[t] - inter;
            float iou = (uni > 0.f) ? (inter / uni) : 0.f;
            if (iou > 0.7f) keep[t] = 0;
        }
        __syncthreads();
    }

    if (t == 0) {
        unsigned char used[NBOX];
        for (int j = 0; j < NBOX; j++) used[j] = 0;
        const int BK4 = BATCH * KTOP * 4;
        const int BK  = BATCH * KTOP;
        for (int k = 0; k < KTOP; k++) {
            float best = -2.f;
            int bi = 0;
            for (int j = 0; j < NBOX; j++) {
                if (used[j]) continue;
                float s = keep[j] ? oc[j] : -1.0f;
                if (s > best) { best = s; bi = j; }
            }
            used[bi] = 1;
            bool valid = best > 0.1f;
            int ob = (b * KTOP + k) * 4;
            if (ob + 3 < out_size) {
                out[ob + 0] = valid ? ox1[bi] : 0.f;
                out[ob + 1] = valid ? oy1[bi] : 0.f;
                out[ob + 2] = valid ? ox2[bi] : 0.f;
                out[ob + 3] = valid ? oy2[bi] : 0.f;
            }
            int ol_idx = BK4 + b * KTOP + k;
            if (ol_idx < out_size) out[ol_idx] = valid ? (float)ol[bi] : 0.f;
            int oc_idx = BK4 + BK + b * KTOP + k;
            if (oc_idx < out_size) out[oc_idx] = valid ? oc[bi] : 0.f;
        }
    }
}

// ---------------- launch ---------------------------------------------------------
extern "C" void kernel_launch(void* const* d_in, const int* in_sizes, int n_in,
                              void* d_out, int out_size) {
    const float* x      = (const float*)d_in[0];
    const float* conv_w = (const float*)d_in[1];
    const float* conv_b = (const float*)d_in[2];
    const float* fc1_w  = (const float*)d_in[3];
    const float* fc1_b  = (const float*)d_in[4];
    const float* fc2_w  = (const float*)d_in[5];
    const float* fc2_b  = (const float*)d_in[6];
    float* out = (float*)d_out;

    float *A0, *part, *act1, *h1;
    cudaGetSymbolAddress((void**)&A0,   g_A0);
    cudaGetSymbolAddress((void**)&part, g_part);
    cudaGetSymbolAddress((void**)&act1, g_act1);
    cudaGetSymbolAddress((void**)&h1,   g_h1);

    cudaFuncSetAttribute(gemm_mma, cudaFuncAttributeMaxDynamicSharedMemorySize,
                         DSMEM_BYTES);

    // 1. gather subsampled input (smem transpose, coalesced writes)
    gather_kernel<<<dim3(20, 256), 256>>>(x);

    // 2. conv GEMM: (12544 x 1280) * (128 x 1280)^T, split-K=3 -> 294 CTAs
    //    kc=448 (multiple of 32); last split covers 384.
    gemm_mma<<<dim3(1, 98, 3), 256, DSMEM_BYTES>>>(A0, conv_w, part,
                                                   12544, 128, 1280, 448, 128);
    reduce_conv<<<(12544 * 128 + 255) / 256, 256>>>(part, conv_b);

    // 3. fc1 GEMM: (256 x 6272) * (4096 x 6272)^T, split-K=4 -> 256 CTAs
    gemm_mma<<<dim3(32, 2, 4), 256, DSMEM_BYTES>>>(act1, fc1_w, part,
                                                   256, 4096, 6272, 1568, 4096);
    reduce_fc1<<<(256 * 4096 + 255) / 256, 256>>>(part, fc1_b);

    // 4. fc2 GEMM: (256 x 4096) * (1470 x 4096)^T, split-K=12 -> 288 CTAs
    gemm_mma<<<dim3(12, 2, 12), 256, DSMEM_BYTES>>>(h1, fc2_w, part,
                                                    256, 1470, 4096, 352, 1536);
    reduce_fc2<<<(256 * 1470 + 255) / 256, 256>>>(part, fc2_b);

    // 5. decode + NMS
    decode_kernel<<<(BATCH * NBOX + 255) / 256, 256>>>();
    nms_kernel<<<BATCH, 128>>>(out, out_size);
}

// round 13
// speedup vs baseline: 1.5151x; 1.5151x over previous
#include <cuda_runtime.h>
#include <math.h>
#include <cstdint>

#define BATCH 256
#define NBOX 98
#define KTOP 10

// ---------------- scratch (static device globals; no allocation) ----------------
__device__ float g_A0[12544 * 1280];       // gathered subsampled input, M x K
__device__ float g_part[3 * 12544 * 128];  // split-K partials (max consumer: conv)
__device__ float g_act1[BATCH * 6272];     // conv output in fc1-input layout
__device__ float g_h1[BATCH * 4096];       // fc1 output (post leaky relu)
__device__ float g_h2[BATCH * 1470];       // fc2 output (post sigmoid)
__device__ float g_boxes[BATCH * NBOX * 4];
__device__ float g_conf[BATCH * NBOX];
__device__ int   g_labels[BATCH * NBOX];

// ---------------- helpers -------------------------------------------------------
__device__ __forceinline__ uint32_t smem_u32(const void* p) {
    uint32_t a;
    asm("{ .reg .u64 t; cvta.to.shared.u64 t, %1; cvt.u32.u64 %0, t; }"
        : "=r"(a) : "l"(p));
    return a;
}
__device__ __forceinline__ void cp4(uint32_t dst, const void* src) {
    asm volatile("cp.async.ca.shared.global [%0], [%1], 4;" :: "r"(dst), "l"(src));
}
#define CP_COMMIT() asm volatile("cp.async.commit_group;" ::: "memory")
#define CP_WAIT4()  asm volatile("cp.async.wait_group 4;" ::: "memory")

// Fast 3xTF32 split: the tensor core reads only the 19 tf32 bits of a .b32
// operand (low 13 mantissa bits ignored). hi = a masked to tf32 bits;
// r = a - hi is exact (Sterbenz); r is fed raw as lo (MMA truncates it).
__device__ __forceinline__ void tf32_split(float a, uint32_t& hi, uint32_t& lo) {
    uint32_t ab = __float_as_uint(a) & 0xFFFFE000u;
    hi = ab;
    lo = __float_as_uint(a - __uint_as_float(ab));
}

__device__ __forceinline__ void mma_tf32(float* c, uint32_t a0, uint32_t a1,
                                         uint32_t a2, uint32_t a3,
                                         uint32_t b0, uint32_t b1) {
    asm volatile(
        "mma.sync.aligned.m16n8k8.row.col.f32.tf32.tf32.f32 "
        "{%0,%1,%2,%3}, {%4,%5,%6,%7}, {%8,%9}, {%0,%1,%2,%3};"
        : "+f"(c[0]), "+f"(c[1]), "+f"(c[2]), "+f"(c[3])
        : "r"(a0), "r"(a1), "r"(a2), "r"(a3), "r"(b0), "r"(b1));
}

// ---------------- gather: x[:, :, ::2, ::2] -> A0[m=b*49+hw][c] ------------------
__global__ void gather_kernel(const float* __restrict__ x) {
    __shared__ float tile[64][50];
    const int b  = blockIdx.y;
    const int c0 = blockIdx.x * 64;
    const int t  = threadIdx.x;
    for (int lin = t; lin < 64 * 49; lin += 256) {
        int c = lin / 49, hw = lin % 49;
        tile[c][hw] =
            x[((size_t)(b * 1280 + c0 + c) * 14 + (hw / 7) * 2) * 14 + (hw % 7) * 2];
    }
    __syncthreads();
    for (int lin = t; lin < 64 * 49; lin += 256) {
        int hw = lin >> 6, c = lin & 63;
        g_A0[((size_t)b * 49 + hw) * 1280 + c0 + c] = tile[c][hw];
    }
}

// ---------------- 3xTF32 mma.sync GEMM, BK=16, 6-stage cp.async pipeline ---------
// CTA tile 128x128; 8 warps: 2(m) x 4(n); warp tile 64x32.
// smem per stage (raw fp32, fragment-major): A 16 segs x 512B, B 16 segs x 512B.
// Stage s at word s*4096: A @ +0, B @ +2048. seg = 128 words = 32 lanes x 16B.
// 6 stages (96KB) + 128 regs -> 2 CTAs/SM; wait_group 4 -> ~5-stage prefetch.
#define STAGE_WORDS 4096
#define NSTAGE 6
#define DSMEM_BYTES (NSTAGE * STAGE_WORDS * 4)

__device__ __forceinline__ void load_stage(
    uint32_t su, int buf, const float* __restrict__ A, const float* __restrict__ B,
    int K, const int* rowA, const int* rowB, int kb, int wid, int lane, int tig)
{
    uint32_t base = su + buf * (STAGE_WORDS * 4);
#pragma unroll
    for (int i = 0; i < 2; i++) {
        int seg = wid + i * 8;
        uint32_t da = base + (uint32_t)(seg * 128 + lane * 4) * 4;
        uint32_t db = da + 2048 * 4;
        const float* sa = A + (size_t)rowA[i] * K + kb + tig;
        const float* sb = B + (size_t)rowB[i] * K + kb + tig;
#pragma unroll
        for (int v = 0; v < 4; v++) {
            cp4(da + v * 4, sa + 4 * v);
            cp4(db + v * 4, sb + 4 * v);
        }
    }
}

__global__ void __launch_bounds__(256, 2)
gemm_mma(const float* __restrict__ A, const float* __restrict__ B,
         float* __restrict__ P, int M, int N, int K, int kc, int Npad) {
    extern __shared__ __align__(16) uint32_t sm[];
    const uint32_t su = smem_u32(sm);

    const int tid  = threadIdx.x;
    const int wid  = tid >> 5;
    const int lane = tid & 31;
    const int g    = lane >> 2;
    const int tig  = lane & 3;
    const int wm   = wid >> 2;
    const int wn   = wid & 3;

    const int m0 = blockIdx.y * 128;
    const int n0 = blockIdx.x * 128;
    const int k0 = blockIdx.z * kc;
    const int nstages = (min(kc, K - k0)) >> 4;

    int rowA[2], rowB[2];
#pragma unroll
    for (int i = 0; i < 2; i++) {
        int sA = wid + i * 8;
        rowA[i] = m0 + (sA >> 1) * 16 + (sA & 1) * 8 + g;
        int nr = n0 + (wid + i * 8) * 8 + g;
        rowB[i] = (nr < N) ? nr : (N - 1);
    }

    float acc[4][4][4];
#pragma unroll
    for (int a = 0; a < 4; a++)
#pragma unroll
        for (int b = 0; b < 4; b++)
#pragma unroll
            for (int c = 0; c < 4; c++) acc[a][b][c] = 0.f;

    // prologue: issue stages 0..4
#pragma unroll
    for (int s = 0; s < 5; s++) {
        if (s < nstages) load_stage(su, s, A, B, K, rowA, rowB, k0 + s * 16,
                                    wid, lane, tig);
        CP_COMMIT();
    }

    for (int t = 0; t < nstages; t++) {
        CP_WAIT4();
        __syncthreads();
        if (t + 5 < nstages)
            load_stage(su, (t + 5) % NSTAGE, A, B, K, rowA, rowB,
                       k0 + (t + 5) * 16, wid, lane, tig);
        CP_COMMIT();

        const uint32_t* sb = sm + (t % NSTAGE) * STAGE_WORDS;

        // ---- B fragments: load raw, mask/sub split ----
        uint32_t Bh[4][4], Bl[4][4];
#pragma unroll
        for (int nt = 0; nt < 4; nt++) {
            uint4 raw = *(const uint4*)&sb[2048 + (wn * 4 + nt) * 128 + lane * 4];
            const float* f = (const float*)&raw;
#pragma unroll
            for (int v = 0; v < 4; v++) tf32_split(f[v], Bh[nt][v], Bl[nt][v]);
        }

#pragma unroll
        for (int mt = 0; mt < 4; mt++) {
            int segLo = ((wm * 4 + mt) * 2) * 128;
            uint4 rlo = *(const uint4*)&sb[segLo + lane * 4];
            uint4 rhi = *(const uint4*)&sb[segLo + 128 + lane * 4];
            const float* flo = (const float*)&rlo;
            const float* fhi = (const float*)&rhi;
            uint32_t HLh[4], HLl[4], HHh[4], HHl[4];
#pragma unroll
            for (int v = 0; v < 4; v++) {
                tf32_split(flo[v], HLh[v], HLl[v]);
                tf32_split(fhi[v], HHh[v], HHl[v]);
            }
#pragma unroll
            for (int s2 = 0; s2 < 2; s2++) {
                const int v0 = 2 * s2, v1 = 2 * s2 + 1;
#pragma unroll
                for (int nt = 0; nt < 4; nt++) {
                    float* c = acc[mt][nt];
                    mma_tf32(c, HLh[v0], HHh[v0], HLh[v1], HHh[v1],
                             Bh[nt][v0], Bh[nt][v1]);
                    mma_tf32(c, HLl[v0], HHl[v0], HLl[v1], HHl[v1],
                             Bh[nt][v0], Bh[nt][v1]);
                    mma_tf32(c, HLh[v0], HHh[v0], HLh[v1], HHh[v1],
                             Bl[nt][v0], Bl[nt][v1]);
                }
            }
        }
    }

    // ---- epilogue: write partials ----
    float* Pz = P + (size_t)blockIdx.z * M * Npad;
    const int mbase = m0 + wm * 64;
    const int nbase = n0 + wn * 32;
#pragma unroll
    for (int mt = 0; mt < 4; mt++) {
#pragma unroll
        for (int nt = 0; nt < 4; nt++) {
            float* c = acc[mt][nt];
            int r = mbase + mt * 16 + g;
            int cc = nbase + nt * 8 + tig * 2;
            *(float2*)&Pz[(size_t)r * Npad + cc]       = make_float2(c[0], c[1]);
            *(float2*)&Pz[(size_t)(r + 8) * Npad + cc] = make_float2(c[2], c[3]);
        }
    }
}

// ---------------- split-K reduces with fused epilogues --------------------------
__global__ void reduce_conv(const float* __restrict__ part,
                            const float* __restrict__ bias) {
    int idx = blockIdx.x * blockDim.x + threadIdx.x;
    if (idx >= 12544 * 128) return;
    const int S = 12544 * 128;
    int col = idx & 127;
    int m   = idx >> 7;
    float v = part[idx] + part[S + idx] + part[2 * S + idx] + bias[col];
    int b = m / 49, hw = m - b * 49;
    g_act1[(size_t)b * 6272 + col * 49 + hw] = v;
}

__global__ void reduce_fc1(const float* __restrict__ part,
                           const float* __restrict__ bias) {
    int idx = blockIdx.x * blockDim.x + threadIdx.x;
    if (idx >= 256 * 4096) return;
    const int S = 256 * 4096;
    int n = idx & 4095;
    float v = part[idx] + part[S + idx] + part[2 * S + idx] + part[3 * S + idx]
            + bias[n];
    g_h1[idx] = (v >= 0.f) ? v : 0.1f * v;
}

__global__ void reduce_fc2(const float* __restrict__ part,
                           const float* __restrict__ bias) {
    int idx = blockIdx.x * blockDim.x + threadIdx.x;
    if (idx >= 256 * 1470) return;
    int m = idx / 1470, n = idx - m * 1470;
    float v = 0.f;
#pragma unroll
    for (int s = 0; s < 12; s++) v += part[(size_t)s * 256 * 1536 + m * 1536 + n];
    v += bias[n];
    g_h2[idx] = 1.f / (1.f + expf(-v));
}

// ---------------- decode: h2 -> boxes / conf / labels ---------------------------
__global__ void decode_kernel() {
    int idx = blockIdx.x * blockDim.x + threadIdx.x;
    if (idx >= BATCH * NBOX) return;
    int b = idx / NBOX, n = idx % NBOX;
    int cell = n >> 1;
    int gi = cell / 7, gj = cell % 7;
    const float* h = g_h2 + (size_t)b * 1470;

    float bx = h[n * 4 + 0], by = h[n * 4 + 1];
    float bw = h[n * 4 + 2], bh = h[n * 4 + 3];
    float cx = bx * 64.f + gi * 64.f;
    float cy = by * 64.f + gj * 64.f;
    float w  = bw * 448.f;
    float hh = bh * 448.f;
    float x1 = fminf(fmaxf(cx - 0.5f * w,  0.f), 448.f);
    float y1 = fminf(fmaxf(cy - 0.5f * hh, 0.f), 448.f);
    float x2 = fminf(fmaxf(cx + 0.5f * w,  0.f), 448.f);
    float y2 = fminf(fmaxf(cy + 0.5f * hh, 0.f), 448.f);

    g_boxes[idx * 4 + 0] = x1;
    g_boxes[idx * 4 + 1] = y1;
    g_boxes[idx * 4 + 2] = x2;
    g_boxes[idx * 4 + 3] = y2;
    g_conf[idx] = h[392 + n];

    const float* cl = h + 490 + cell * 20;
    float best = cl[0];
    int lab = 0;
#pragma unroll
    for (int c = 1; c < 20; c++) {
        float v = cl[c];
        if (v > best) { best = v; lab = c; }  // first max wins (matches jnp.argmax)
    }
    g_labels[idx] = lab;
}

// ---------------- NMS: one block per image --------------------------------------
__global__ void __launch_bounds__(128)
nms_kernel(float* __restrict__ out, int out_size) {
    int b = blockIdx.x;
    int t = threadIdx.x;

    __shared__ float sc[NBOX], sx1[NBOX], sy1[NBOX], sx2[NBOX], sy2[NBOX];
    __shared__ int   sl[NBOX], order[NBOX];
    __shared__ float oc[NBOX], ox1[NBOX], oy1[NBOX], ox2[NBOX], oy2[NBOX], oarea[NBOX];
    __shared__ int   ol[NBOX];
    __shared__ unsigned char keep[NBOX];

    if (t < NBOX) {
        int g = b * NBOX + t;
        sc[t]  = g_conf[g];
        sl[t]  = g_labels[g];
        sx1[t] = g_boxes[g * 4 + 0];
        sy1[t] = g_boxes[g * 4 + 1];
        sx2[t] = g_boxes[g * 4 + 2];
        sy2[t] = g_boxes[g * 4 + 3];
    }
    __syncthreads();

    if (t < NBOX) {
        float c = sc[t];
        int r = 0;
        for (int j = 0; j < NBOX; j++) {
            float cj = sc[j];
            r += (cj > c) || (cj == c && j < t);
        }
        order[r] = t;
    }
    __syncthreads();

    if (t < NBOX) {
        int s = order[t];
        oc[t] = sc[s];  ol[t] = sl[s];
        ox1[t] = sx1[s]; oy1[t] = sy1[s];
        ox2[t] = sx2[s]; oy2[t] = sy2[s];
        oarea[t] = fmaxf(ox2[t] - ox1[t], 0.f) * fmaxf(oy2[t] - oy1[t], 0.f);
        keep[t] = (oc[t] > 0.1f) ? (unsigned char)1 : (unsigned char)0;
    }
    __syncthreads();

    for (int i = 0; i < NBOX; i++) {
        if (keep[i] && t < NBOX && t > i) {
            float ix1 = fmaxf(ox1[i], ox1[t]);
            float iy1 = fmaxf(oy1[i], oy1[t]);
            float ix2 = fminf(ox2[i], ox2[t]);
            float iy2 = fminf(oy2[i], oy2[t]);
            float inter = fmaxf(ix2 - ix1, 0.f) * fmaxf(iy2 - iy1, 0.f);
            float uni = oarea[i] + oarea[t] - inter;
            float iou = (uni > 0.f) ? (inter / uni) : 0.f;
            if (iou > 0.7f) keep[t] = 0;
        }
        __syncthreads();
    }

    if (t == 0) {
        unsigned char used[NBOX];
        for (int j = 0; j < NBOX; j++) used[j] = 0;
        const int BK4 = BATCH * KTOP * 4;
        const int BK  = BATCH * KTOP;
        for (int k = 0; k < KTOP; k++) {
            float best = -2.f;
            int bi = 0;
            for (int j = 0; j < NBOX; j++) {
                if (used[j]) continue;
                float s = keep[j] ? oc[j] : -1.0f;
                if (s > best) { best = s; bi = j; }
            }
            used[bi] = 1;
            bool valid = best > 0.1f;
            int ob = (b * KTOP + k) * 4;
            if (ob + 3 < out_size) {
                out[ob + 0] = valid ? ox1[bi] : 0.f;
                out[ob + 1] = valid ? oy1[bi] : 0.f;
                out[ob + 2] = valid ? ox2[bi] : 0.f;
                out[ob + 3] = valid ? oy2[bi] : 0.f;
            }
            int ol_idx = BK4 + b * KTOP + k;
            if (ol_idx < out_size) out[ol_idx] = valid ? (float)ol[bi] : 0.f;
            int oc_idx = BK4 + BK + b * KTOP + k;
            if (oc_idx < out_size) out[oc_idx] = valid ? oc[bi] : 0.f;
        }
    }
}

// ---------------- launch ---------------------------------------------------------
extern "C" void kernel_launch(void* const* d_in, const int* in_sizes, int n_in,
                              void* d_out, int out_size) {
    const float* x      = (const float*)d_in[0];
    const float* conv_w = (const float*)d_in[1];
    const float* conv_b = (const float*)d_in[2];
    const float* fc1_w  = (const float*)d_in[3];
    const float* fc1_b  = (const float*)d_in[4];
    const float* fc2_w  = (const float*)d_in[5];
    const float* fc2_b  = (const float*)d_in[6];
    float* out = (float*)d_out;

    float *A0, *part, *act1, *h1;
    cudaGetSymbolAddress((void**)&A0,   g_A0);
    cudaGetSymbolAddress((void**)&part, g_part);
    cudaGetSymbolAddress((void**)&act1, g_act1);
    cudaGetSymbolAddress((void**)&h1,   g_h1);

    cudaFuncSetAttribute(gemm_mma, cudaFuncAttributeMaxDynamicSharedMemorySize,
                         DSMEM_BYTES);

    // 1. gather subsampled input (smem transpose, coalesced writes)
    gather_kernel<<<dim3(20, 256), 256>>>(x);

    // 2. conv GEMM: (12544 x 1280) * (128 x 1280)^T, split-K=3 -> 294 CTAs
    gemm_mma<<<dim3(1, 98, 3), 256, DSMEM_BYTES>>>(A0, conv_w, part,
                                                   12544, 128, 1280, 432, 128);
    reduce_conv<<<(12544 * 128 + 255) / 256, 256>>>(part, conv_b);

    // 3. fc1 GEMM: (256 x 6272) * (4096 x 6272)^T, split-K=4 -> 256 CTAs
    gemm_mma<<<dim3(32, 2, 4), 256, DSMEM_BYTES>>>(act1, fc1_w, part,
                                                   256, 4096, 6272, 1568, 4096);
    reduce_fc1<<<(256 * 4096 + 255) / 256, 256>>>(part, fc1_b);

    // 4. fc2 GEMM: (256 x 4096) * (1470 x 4096)^T, split-K=12 -> 288 CTAs
    gemm_mma<<<dim3(12, 2, 12), 256, DSMEM_BYTES>>>(h1, fc2_w, part,
                                                    256, 1470, 4096, 352, 1536);
    reduce_fc2<<<(256 * 1470 + 255) / 256, 256>>>(part, fc2_b);

    // 5. decode + NMS
    decode_kernel<<<(BATCH * NBOX + 255) / 256, 256>>>();
    nms_kernel<<<BATCH, 128>>>(out, out_size);
}

// round 14
// speedup vs baseline: 2.1925x; 1.4471x over previous
#include <cuda_runtime.h>
#include <math.h>
#include <cstdint>

#define BATCH 256
#define NBOX 98
#define KTOP 10

// ---------------- scratch (static device globals; no allocation) ----------------
__device__ float g_A0[12544 * 1280];       // gathered subsampled input, M x K
__device__ float g_part[3 * 12544 * 128];  // split-K partials (max consumer: conv)
__device__ float g_act1[BATCH * 6272];     // conv output in fc1-input layout
__device__ float g_h1[BATCH * 4096];       // fc1 output (post leaky relu)
__device__ float g_h2[BATCH * 1470];       // fc2 output (post sigmoid)
__device__ float g_boxes[BATCH * NBOX * 4];
__device__ float g_conf[BATCH * NBOX];
__device__ int   g_labels[BATCH * NBOX];

// ---------------- helpers -------------------------------------------------------
__device__ __forceinline__ uint32_t smem_u32(const void* p) {
    uint32_t a;
    asm("{ .reg .u64 t; cvta.to.shared.u64 t, %1; cvt.u32.u64 %0, t; }"
        : "=r"(a) : "l"(p));
    return a;
}
__device__ __forceinline__ void cp8(uint32_t dst, const void* src) {
    asm volatile("cp.async.ca.shared.global [%0], [%1], 8;" :: "r"(dst), "l"(src));
}
#define CP_COMMIT() asm volatile("cp.async.commit_group;" ::: "memory")
#define CP_WAIT2()  asm volatile("cp.async.wait_group 2;" ::: "memory")

// ---- 3xBF16 split helpers ----
// hi = a truncated to bf16 (top 16 bits; exactly what the tensor core reads);
// lo = a - hi (exact, Sterbenz), rounded to bf16. Effective ~17 mantissa bits.
__device__ __forceinline__ float sub_hi(float a) {
    return a - __uint_as_float(__float_as_uint(a) & 0xFFFF0000u);
}
// pack bf16x2 from the top halves of two fp32 bit patterns: {lo16=x>>16, hi16=y>>16}
__device__ __forceinline__ uint32_t prmt_hi(uint32_t x, uint32_t y) {
    uint32_t r;
    asm("prmt.b32 %0, %1, %2, 0x7632;" : "=r"(r) : "r"(x), "r"(y));
    return r;
}
// pack bf16x2 = {hi16=cvt(h), lo16=cvt(l)} with round-nearest
__device__ __forceinline__ uint32_t cvt_bf16x2(float h, float l) {
    uint32_t r;
    asm("cvt.rn.bf16x2.f32 %0, %1, %2;" : "=r"(r) : "f"(h), "f"(l));
    return r;
}

__device__ __forceinline__ void mma_bf16(float* c, uint32_t a0, uint32_t a1,
                                         uint32_t a2, uint32_t a3,
                                         uint32_t b0, uint32_t b1) {
    asm volatile(
        "mma.sync.aligned.m16n8k16.row.col.f32.bf16.bf16.f32 "
        "{%0,%1,%2,%3}, {%4,%5,%6,%7}, {%8,%9}, {%0,%1,%2,%3};"
        : "+f"(c[0]), "+f"(c[1]), "+f"(c[2]), "+f"(c[3])
        : "r"(a0), "r"(a1), "r"(a2), "r"(a3), "r"(b0), "r"(b1));
}

// ---------------- gather: x[:, :, ::2, ::2] -> A0[m=b*49+hw][c] ------------------
__global__ void gather_kernel(const float* __restrict__ x) {
    __shared__ float tile[64][50];
    const int b  = blockIdx.y;
    const int c0 = blockIdx.x * 64;
    const int t  = threadIdx.x;
    for (int lin = t; lin < 64 * 49; lin += 256) {
        int c = lin / 49, hw = lin % 49;
        tile[c][hw] =
            x[((size_t)(b * 1280 + c0 + c) * 14 + (hw / 7) * 2) * 14 + (hw % 7) * 2];
    }
    __syncthreads();
    for (int lin = t; lin < 64 * 49; lin += 256) {
        int hw = lin >> 6, c = lin & 63;
        g_A0[((size_t)b * 49 + hw) * 1280 + c0 + c] = tile[c][hw];
    }
}

// ---------------- 3xBF16 mma.sync GEMM, BK=16, 4-stage cp.async pipeline ---------
// CTA tile 128x128; 8 warps: 2(m) x 4(n); warp tile 64x32.
// smem per stage (raw fp32, fragment-major): A 16 segs x 512B, B 16 segs x 512B.
// Stage s at word s*4096: A @ +0, B @ +2048. seg = 128 words = 32 lanes x 16B.
// Per-lane k layout within a seg row: {2tig, 2tig+1, 2tig+8, 2tig+9} — the exact
// m16n8k16 fragment k-pairs. Each (term,mt,nt) is ONE k16 bf16 MMA per stage.
#define STAGE_WORDS 4096
#define DSMEM_BYTES (4 * STAGE_WORDS * 4)

__device__ __forceinline__ void load_stage(
    uint32_t su, int buf, const float* __restrict__ A, const float* __restrict__ B,
    int K, const int* rowA, const int* rowB, int kb, int wid, int lane, int tig)
{
    uint32_t base = su + buf * (STAGE_WORDS * 4);
#pragma unroll
    for (int i = 0; i < 2; i++) {
        int seg = wid + i * 8;
        uint32_t da = base + (uint32_t)(seg * 128 + lane * 4) * 4;
        uint32_t db = da + 2048 * 4;
        const float* sa = A + (size_t)rowA[i] * K + kb + 2 * tig;
        const float* sb = B + (size_t)rowB[i] * K + kb + 2 * tig;
        cp8(da,     sa);       // k = 2tig, 2tig+1
        cp8(da + 8, sa + 8);   // k = 2tig+8, 2tig+9
        cp8(db,     sb);
        cp8(db + 8, sb + 8);
    }
}

__global__ void __launch_bounds__(256, 2)
gemm_mma(const float* __restrict__ A, const float* __restrict__ B,
         float* __restrict__ P, int M, int N, int K, int kc, int Npad) {
    extern __shared__ __align__(16) uint32_t sm[];
    const uint32_t su = smem_u32(sm);

    const int tid  = threadIdx.x;
    const int wid  = tid >> 5;
    const int lane = tid & 31;
    const int g    = lane >> 2;
    const int tig  = lane & 3;
    const int wm   = wid >> 2;
    const int wn   = wid & 3;

    const int m0 = blockIdx.y * 128;
    const int n0 = blockIdx.x * 128;
    const int k0 = blockIdx.z * kc;
    const int nstages = (min(kc, K - k0)) >> 4;

    int rowA[2], rowB[2];
#pragma unroll
    for (int i = 0; i < 2; i++) {
        int sA = wid + i * 8;
        rowA[i] = m0 + (sA >> 1) * 16 + (sA & 1) * 8 + g;
        int nr = n0 + (wid + i * 8) * 8 + g;
        rowB[i] = (nr < N) ? nr : (N - 1);
    }

    float acc[4][4][4];
#pragma unroll
    for (int a = 0; a < 4; a++)
#pragma unroll
        for (int b = 0; b < 4; b++)
#pragma unroll
            for (int c = 0; c < 4; c++) acc[a][b][c] = 0.f;

    // prologue: issue stages 0..2
#pragma unroll
    for (int s = 0; s < 3; s++) {
        if (s < nstages) load_stage(su, s, A, B, K, rowA, rowB, k0 + s * 16,
                                    wid, lane, tig);
        CP_COMMIT();
    }

    for (int t = 0; t < nstages; t++) {
        CP_WAIT2();
        __syncthreads();
        if (t + 3 < nstages)
            load_stage(su, (t + 3) & 3, A, B, K, rowA, rowB, k0 + (t + 3) * 16,
                       wid, lane, tig);
        CP_COMMIT();

        const uint32_t* sb = sm + (t & 3) * STAGE_WORDS;

        // ---- B fragments: hi via PRMT pack, lo via FADD+CVT pack ----
        uint32_t Bh[4][2], Bl[4][2];
#pragma unroll
        for (int nt = 0; nt < 4; nt++) {
            uint4 raw = *(const uint4*)&sb[2048 + (wn * 4 + nt) * 128 + lane * 4];
            const float* f = (const float*)&raw;
            const uint32_t* u = (const uint32_t*)&raw;
            Bh[nt][0] = prmt_hi(u[0], u[1]);
            Bh[nt][1] = prmt_hi(u[2], u[3]);
            Bl[nt][0] = cvt_bf16x2(sub_hi(f[1]), sub_hi(f[0]));
            Bl[nt][1] = cvt_bf16x2(sub_hi(f[3]), sub_hi(f[2]));
        }

#pragma unroll
        for (int mt = 0; mt < 4; mt++) {
            int segLo = ((wm * 4 + mt) * 2) * 128;
            uint4 rlo = *(const uint4*)&sb[segLo + lane * 4];        // row g
            uint4 rhi = *(const uint4*)&sb[segLo + 128 + lane * 4];  // row g+8
            const float* flo = (const float*)&rlo;
            const float* fhi = (const float*)&rhi;
            const uint32_t* ulo = (const uint32_t*)&rlo;
            const uint32_t* uhi = (const uint32_t*)&rhi;

            uint32_t Ah0 = prmt_hi(ulo[0], ulo[1]);   // row g,   k pair 0
            uint32_t Ah1 = prmt_hi(uhi[0], uhi[1]);   // row g+8, k pair 0
            uint32_t Ah2 = prmt_hi(ulo[2], ulo[3]);   // row g,   k pair 1 (+8)
            uint32_t Ah3 = prmt_hi(uhi[2], uhi[3]);   // row g+8, k pair 1
            uint32_t Al0 = cvt_bf16x2(sub_hi(flo[1]), sub_hi(flo[0]));
            uint32_t Al1 = cvt_bf16x2(sub_hi(fhi[1]), sub_hi(fhi[0]));
            uint32_t Al2 = cvt_bf16x2(sub_hi(flo[3]), sub_hi(flo[2]));
            uint32_t Al3 = cvt_bf16x2(sub_hi(fhi[3]), sub_hi(fhi[2]));

#pragma unroll
            for (int nt = 0; nt < 4; nt++) {
                float* c = acc[mt][nt];
                mma_bf16(c, Ah0, Ah1, Ah2, Ah3, Bh[nt][0], Bh[nt][1]);
                mma_bf16(c, Al0, Al1, Al2, Al3, Bh[nt][0], Bh[nt][1]);
                mma_bf16(c, Ah0, Ah1, Ah2, Ah3, Bl[nt][0], Bl[nt][1]);
            }
        }
    }

    // ---- epilogue: write partials (same m16n8 accum layout as before) ----
    float* Pz = P + (size_t)blockIdx.z * M * Npad;
    const int mbase = m0 + wm * 64;
    const int nbase = n0 + wn * 32;
#pragma unroll
    for (int mt = 0; mt < 4; mt++) {
#pragma unroll
        for (int nt = 0; nt < 4; nt++) {
            float* c = acc[mt][nt];
            int r = mbase + mt * 16 + g;
            int cc = nbase + nt * 8 + tig * 2;
            *(float2*)&Pz[(size_t)r * Npad + cc]       = make_float2(c[0], c[1]);
            *(float2*)&Pz[(size_t)(r + 8) * Npad + cc] = make_float2(c[2], c[3]);
        }
    }
}

// ---------------- split-K reduces with fused epilogues --------------------------
__global__ void reduce_conv(const float* __restrict__ part,
                            const float* __restrict__ bias) {
    int idx = blockIdx.x * blockDim.x + threadIdx.x;
    if (idx >= 12544 * 128) return;
    const int S = 12544 * 128;
    int col = idx & 127;
    int m   = idx >> 7;
    float v = part[idx] + part[S + idx] + part[2 * S + idx] + bias[col];
    int b = m / 49, hw = m - b * 49;
    g_act1[(size_t)b * 6272 + col * 49 + hw] = v;
}

__global__ void reduce_fc1(const float* __restrict__ part,
                           const float* __restrict__ bias) {
    int idx = blockIdx.x * blockDim.x + threadIdx.x;
    if (idx >= 256 * 4096) return;
    const int S = 256 * 4096;
    int n = idx & 4095;
    float v = part[idx] + part[S + idx] + part[2 * S + idx] + part[3 * S + idx]
            + bias[n];
    g_h1[idx] = (v >= 0.f) ? v : 0.1f * v;
}

__global__ void reduce_fc2(const float* __restrict__ part,
                           const float* __restrict__ bias) {
    int idx = blockIdx.x * blockDim.x + threadIdx.x;
    if (idx >= 256 * 1470) return;
    int m = idx / 1470, n = idx - m * 1470;
    float v = 0.f;
#pragma unroll
    for (int s = 0; s < 12; s++) v += part[(size_t)s * 256 * 1536 + m * 1536 + n];
    v += bias[n];
    g_h2[idx] = 1.f / (1.f + expf(-v));
}

// ---------------- decode: h2 -> boxes / conf / labels ---------------------------
__global__ void decode_kernel() {
    int idx = blockIdx.x * blockDim.x + threadIdx.x;
    if (idx >= BATCH * NBOX) return;
    int b = idx / NBOX, n = idx % NBOX;
    int cell = n >> 1;
    int gi = cell / 7, gj = cell % 7;
    const float* h = g_h2 + (size_t)b * 1470;

    float bx = h[n * 4 + 0], by = h[n * 4 + 1];
    float bw = h[n * 4 + 2], bh = h[n * 4 + 3];
    float cx = bx * 64.f + gi * 64.f;
    float cy = by * 64.f + gj * 64.f;
    float w  = bw * 448.f;
    float hh = bh * 448.f;
    float x1 = fminf(fmaxf(cx - 0.5f * w,  0.f), 448.f);
    float y1 = fminf(fmaxf(cy - 0.5f * hh, 0.f), 448.f);
    float x2 = fminf(fmaxf(cx + 0.5f * w,  0.f), 448.f);
    float y2 = fminf(fmaxf(cy + 0.5f * hh, 0.f), 448.f);

    g_boxes[idx * 4 + 0] = x1;
    g_boxes[idx * 4 + 1] = y1;
    g_boxes[idx * 4 + 2] = x2;
    g_boxes[idx * 4 + 3] = y2;
    g_conf[idx] = h[392 + n];

    const float* cl = h + 490 + cell * 20;
    float best = cl[0];
    int lab = 0;
#pragma unroll
    for (int c = 1; c < 20; c++) {
        float v = cl[c];
        if (v > best) { best = v; lab = c; }  // first max wins (matches jnp.argmax)
    }
    g_labels[idx] = lab;
}

// ---------------- NMS: one block per image --------------------------------------
__global__ void __launch_bounds__(128)
nms_kernel(float* __restrict__ out, int out_size) {
    int b = blockIdx.x;
    int t = threadIdx.x;

    __shared__ float sc[NBOX], sx1[NBOX], sy1[NBOX], sx2[NBOX], sy2[NBOX];
    __shared__ int   sl[NBOX], order[NBOX];
    __shared__ float oc[NBOX], ox1[NBOX], oy1[NBOX], ox2[NBOX], oy2[NBOX], oarea[NBOX];
    __shared__ int   ol[NBOX];
    __shared__ unsigned char keep[NBOX];

    if (t < NBOX) {
        int g = b * NBOX + t;
        sc[t]  = g_conf[g];
        sl[t]  = g_labels[g];
        sx1[t] = g_boxes[g * 4 + 0];
        sy1[t] = g_boxes[g * 4 + 1];
        sx2[t] = g_boxes[g * 4 + 2];
        sy2[t] = g_boxes[g * 4 + 3];
    }
    __syncthreads();

    if (t < NBOX) {
        float c = sc[t];
        int r = 0;
        for (int j = 0; j < NBOX; j++) {
            float cj = sc[j];
            r += (cj > c) || (cj == c && j < t);
        }
        order[r] = t;
    }
    __syncthreads();

    if (t < NBOX) {
        int s = order[t];
        oc[t] = sc[s];  ol[t] = sl[s];
        ox1[t] = sx1[s]; oy1[t] = sy1[s];
        ox2[t] = sx2[s]; oy2[t] = sy2[s];
        oarea[t] = fmaxf(ox2[t] - ox1[t], 0.f) * fmaxf(oy2[t] - oy1[t], 0.f);
        keep[t] = (oc[t] > 0.1f) ? (unsigned char)1 : (unsigned char)0;
    }
    __syncthreads();

    for (int i = 0; i < NBOX; i++) {
        if (keep[i] && t < NBOX && t > i) {
            float ix1 = fmaxf(ox1[i], ox1[t]);
            float iy1 = fmaxf(oy1[i], oy1[t]);
            float ix2 = fminf(ox2[i], ox2[t]);
            float iy2 = fminf(oy2[i], oy2[t]);
            float inter = fmaxf(ix2 - ix1, 0.f) * fmaxf(iy2 - iy1, 0.f);
            float uni = oarea[i] + oarea[t] - inter;
            float iou = (uni > 0.f) ? (inter / uni) : 0.f;
            if (iou > 0.7f) keep[t] = 0;
        }
        __syncthreads();
    }

    if (t == 0) {
        unsigned char used[NBOX];
        for (int j = 0; j < NBOX; j++) used[j] = 0;
        const int BK4 = BATCH * KTOP * 4;
        const int BK  = BATCH * KTOP;
        for (int k = 0; k < KTOP; k++) {
            float best = -2.f;
            int bi = 0;
            for (int j = 0; j < NBOX; j++) {
                if (used[j]) continue;
                float s = keep[j] ? oc[j] : -1.0f;
                if (s > best) { best = s; bi = j; }
            }
            used[bi] = 1;
            bool valid = best > 0.1f;
            int ob = (b * KTOP + k) * 4;
            if (ob + 3 < out_size) {
                out[ob + 0] = valid ? ox1[bi] : 0.f;
                out[ob + 1] = valid ? oy1[bi] : 0.f;
                out[ob + 2] = valid ? ox2[bi] : 0.f;
                out[ob + 3] = valid ? oy2[bi] : 0.f;
            }
            int ol_idx = BK4 + b * KTOP + k;
            if (ol_idx < out_size) out[ol_idx] = valid ? (float)ol[bi] : 0.f;
            int oc_idx = BK4 + BK + b * KTOP + k;
            if (oc_idx < out_size) out[oc_idx] = valid ? oc[bi] : 0.f;
        }
    }
}

// ---------------- launch ---------------------------------------------------------
extern "C" void kernel_launch(void* const* d_in, const int* in_sizes, int n_in,
                              void* d_out, int out_size) {
    const float* x      = (const float*)d_in[0];
    const float* conv_w = (const float*)d_in[1];
    const float* conv_b = (const float*)d_in[2];
    const float* fc1_w  = (const float*)d_in[3];
    const float* fc1_b  = (const float*)d_in[4];
    const float* fc2_w  = (const float*)d_in[5];
    const float* fc2_b  = (const float*)d_in[6];
    float* out = (float*)d_out;

    float *A0, *part, *act1, *h1;
    cudaGetSymbolAddress((void**)&A0,   g_A0);
    cudaGetSymbolAddress((void**)&part, g_part);
    cudaGetSymbolAddress((void**)&act1, g_act1);
    cudaGetSymbolAddress((void**)&h1,   g_h1);

    cudaFuncSetAttribute(gemm_mma, cudaFuncAttributeMaxDynamicSharedMemorySize,
                         DSMEM_BYTES);

    // 1. gather subsampled input (smem transpose, coalesced writes)
    gather_kernel<<<dim3(20, 256), 256>>>(x);

    // 2. conv GEMM: (12544 x 1280) * (128 x 1280)^T, split-K=3 -> 294 CTAs
    gemm_mma<<<dim3(1, 98, 3), 256, DSMEM_BYTES>>>(A0, conv_w, part,
                                                   12544, 128, 1280, 432, 128);
    reduce_conv<<<(12544 * 128 + 255) / 256, 256>>>(part, conv_b);

    // 3. fc1 GEMM: (256 x 6272) * (4096 x 6272)^T, split-K=4 -> 256 CTAs
    gemm_mma<<<dim3(32, 2, 4), 256, DSMEM_BYTES>>>(act1, fc1_w, part,
                                                   256, 4096, 6272, 1568, 4096);
    reduce_fc1<<<(256 * 4096 + 255) / 256, 256>>>(part, fc1_b);

    // 4. fc2 GEMM: (256 x 4096) * (1470 x 4096)^T, split-K=12 -> 288 CTAs
    gemm_mma<<<dim3(12, 2, 12), 256, DSMEM_BYTES>>>(h1, fc2_w, part,
                                                    256, 1470, 4096, 352, 1536);
    reduce_fc2<<<(256 * 1470 + 255) / 256, 256>>>(part, fc2_b);

    // 5. decode + NMS
    decode_kernel<<<(BATCH * NBOX + 255) / 256, 256>>>();
    nms_kernel<<<BATCH, 128>>>(out, out_size);
}